// round 1
// baseline (speedup 1.0000x reference)
#include <cuda_runtime.h>
#include <cuda_bf16.h>

#define NN   50000
#define NE   800000
#define FIN  128
#define FH   64
#define FOUT 64
#define KC   1024

// ---------------- scratch (device globals; no allocation) ----------------
__device__ __align__(16) float g_h[NN * FH];      // x @ W1
__device__ __align__(16) float g_agg[NN * FH];    // neighbor aggregation
__device__ __align__(16) float g_x1[NN * FH];     // relu(gcn1)
__device__ float g_deg[NN];
__device__ float g_dinv[NN];
__device__ __align__(16) float g_psum[KC * FH];   // cluster sums
__device__ float g_pcnt[KC];
__device__ float g_A[KC * KC];                    // pooled adjacency (0/1)
__device__ float g_degp[KC];
__device__ __align__(16) float g_hps[KC * FH];    // dinv_p[s] * (x_p @ W2)
__device__ __align__(16) float g_xp2[KC * FOUT];  // pooled conv output

// ---------------- helpers ----------------
__device__ __forceinline__ unsigned long long pack2(float x, float y) {
    unsigned long long r;
    asm("mov.b64 %0, {%1, %2};" : "=l"(r) : "f"(x), "f"(y));
    return r;
}
__device__ __forceinline__ float2 unpack2(unsigned long long v) {
    float2 f;
    asm("mov.b64 {%0, %1}, %2;" : "=f"(f.x), "=f"(f.y) : "l"(v));
    return f;
}
__device__ __forceinline__ void ffma2(unsigned long long& d, unsigned long long a,
                                      unsigned long long b) {
    asm("fma.rn.f32x2 %0, %1, %2, %0;" : "+l"(d) : "l"(a), "l"(b));
}
__device__ __forceinline__ void red4(float* p, float4 v) {
    asm volatile("red.global.add.v4.f32 [%0], {%1,%2,%3,%4};"
                 :: "l"(p), "f"(v.x), "f"(v.y), "f"(v.z), "f"(v.w) : "memory");
}

// ---------------- kernels ----------------
__global__ void zero_all_kernel() {
    int i = blockIdx.x * blockDim.x + threadIdx.x;      // grid covers 3.2M
    if (i < NN) g_deg[i] = 0.f;
    if (i < NN * FH) g_agg[i] = 0.f;
    if (i < KC * FH) g_psum[i] = 0.f;
    if (i < KC) { g_pcnt[i] = 0.f; g_degp[i] = 0.f; }
    if (i < KC * KC) g_A[i] = 0.f;
}

__global__ void deg_kernel(const int* __restrict__ dst) {
    int e = blockIdx.x * blockDim.x + threadIdx.x;
    if (e < NE) atomicAdd(&g_deg[dst[e]], 1.0f);
}

__global__ void dinv_kernel() {
    int i = blockIdx.x * blockDim.x + threadIdx.x;
    if (i < NN) g_dinv[i] = rsqrtf(g_deg[i] + 1.0f);
}

// h = x @ W1 : [50000,128] @ [128,64].  One warp computes 4 rows, lane owns
// 2 output cols via packed f32x2 FMA.  W1 lives in smem (32KB).
__global__ void __launch_bounds__(256) gemm1_kernel(const float* __restrict__ x,
                                                    const float* __restrict__ W1) {
    __shared__ float Ws[FIN * FH];      // 32KB
    __shared__ float xs[8][4][FIN];     // 16KB
    for (int i = threadIdx.x; i < FIN * FH; i += 256) Ws[i] = W1[i];
    __syncthreads();

    int warp = threadIdx.x >> 5, lane = threadIdx.x & 31;
    int nwarps = gridDim.x * 8;
    const int ntasks = (NN + 3) / 4;    // 12500
    for (int t = blockIdx.x * 8 + warp; t < ntasks; t += nwarps) {
        int row0 = t * 4;
        #pragma unroll
        for (int u = 0; u < 4; u++) {   // row u, float4 col = lane
            int gr = row0 + u;
            float4 v = make_float4(0.f, 0.f, 0.f, 0.f);
            if (gr < NN) v = ((const float4*)x)[gr * (FIN / 4) + lane];
            ((float4*)&xs[warp][u][0])[lane] = v;
        }
        __syncwarp();
        unsigned long long acc[4] = {0ull, 0ull, 0ull, 0ull};
        #pragma unroll 4
        for (int k = 0; k < FIN; k++) {
            unsigned long long w = *(const unsigned long long*)&Ws[k * FH + 2 * lane];
            #pragma unroll
            for (int r = 0; r < 4; r++) {
                float xv = xs[warp][r][k];
                ffma2(acc[r], pack2(xv, xv), w);
            }
        }
        #pragma unroll
        for (int r = 0; r < 4; r++) {
            int gr = row0 + r;
            if (gr < NN) *(float2*)&g_h[gr * FH + 2 * lane] = unpack2(acc[r]);
        }
        __syncwarp();
    }
}

// agg[dst] += norm * h[src] ; 16 lanes per edge, float4 per lane, vector red.
__global__ void edge_agg_kernel(const int* __restrict__ src, const int* __restrict__ dst) {
    int tid = blockIdx.x * blockDim.x + threadIdx.x;
    int e = tid >> 4, q = tid & 15;
    if (e >= NE) return;
    int s = src[e], d = dst[e];
    float norm = g_dinv[s] * g_dinv[d];
    float4 h4 = ((const float4*)g_h)[s * 16 + q];
    float4 v = make_float4(h4.x * norm, h4.y * norm, h4.z * norm, h4.w * norm);
    red4(&g_agg[d * FH + q * 4], v);
}

// x1 = relu(agg + dinv^2*h + b1) ; fused cluster-pool scatter.
__global__ void x1_pool_kernel(const int* __restrict__ cluster, const float* __restrict__ b1) {
    int tid = blockIdx.x * blockDim.x + threadIdx.x;
    int n = tid >> 4, q = tid & 15;
    if (n >= NN) return;
    float di = g_dinv[n];
    float selfw = di * di;
    float4 a  = ((const float4*)g_agg)[n * 16 + q];
    float4 h4 = ((const float4*)g_h)[n * 16 + q];
    float4 b  = ((const float4*)b1)[q];
    float4 v;
    v.x = fmaxf(a.x + selfw * h4.x + b.x, 0.f);
    v.y = fmaxf(a.y + selfw * h4.y + b.y, 0.f);
    v.z = fmaxf(a.z + selfw * h4.z + b.z, 0.f);
    v.w = fmaxf(a.w + selfw * h4.w + b.w, 0.f);
    ((float4*)g_x1)[n * 16 + q] = v;
    int c = cluster[n];
    red4(&g_psum[c * FH + q * 4], v);
    if (q == 0) atomicAdd(&g_pcnt[c], 1.0f);
}

// dense pooled adjacency: idempotent 1.0 stores (races benign)
__global__ void a_mat_kernel(const int* __restrict__ src, const int* __restrict__ dst,
                             const int* __restrict__ cluster) {
    int e = blockIdx.x * blockDim.x + threadIdx.x;
    if (e < NE) {
        int cu = cluster[src[e]], cv = cluster[dst[e]];
        g_A[cu * KC + cv] = 1.0f;
    }
}

__global__ void a_diag_kernel() {
    int t = blockIdx.x * blockDim.x + threadIdx.x;
    if (t < KC) g_A[t * KC + t] = 1.0f;   // A*(1-I)+I => diag exactly 1
}

// deg_p[t] = column sums of A_hat
__global__ void degp_kernel() {
    int t = blockIdx.x * 256 + threadIdx.x;   // blockIdx.x in 0..3
    int s0 = blockIdx.y * 64;
    float sum = 0.f;
    #pragma unroll 8
    for (int i = 0; i < 64; i++) sum += g_A[(s0 + i) * KC + t];
    atomicAdd(&g_degp[t], sum);
}

// x_p = psum/cnt ; hps = dinv_p[k] * (x_p @ W2)
__global__ void hp_kernel(const float* __restrict__ W2) {
    __shared__ float xp[FH];
    int k = blockIdx.x, f = threadIdx.x;    // 64 threads
    float cnt = fmaxf(g_pcnt[k], 1.0f);
    xp[f] = g_psum[k * FH + f] / cnt;
    __syncthreads();
    float acc = 0.f;
    #pragma unroll
    for (int j = 0; j < FH; j++) acc += xp[j] * W2[j * FOUT + f];
    g_hps[k * FH + f] = acc * rsqrtf(g_degp[k]);
}

// x_p2[t,f] = dinv_p[t] * sum_s A_hat[s,t]*hps[s,f] + b2[f]
// block: 8 target cols, threads (f=64, g=4) with g owning 2 targets
__global__ void __launch_bounds__(256) xp2_kernel(const float* __restrict__ b2) {
    __shared__ float As[64][8];
    __shared__ float Hs[64][FH];    // 16KB
    int t0 = blockIdx.x * 8;        // 128 blocks
    int f = threadIdx.x & 63, g = threadIdx.x >> 6;   // g: 0..3
    float acc[2] = {0.f, 0.f};
    for (int s0 = 0; s0 < KC; s0 += 64) {
        __syncthreads();
        for (int i = threadIdx.x; i < 64 * 8; i += 256) {
            int si = i >> 3, tj = i & 7;
            As[si][tj] = g_A[(s0 + si) * KC + t0 + tj];
        }
        for (int i = threadIdx.x; i < 64 * 64; i += 256)
            Hs[i >> 6][i & 63] = g_hps[(s0 + (i >> 6)) * FH + (i & 63)];
        __syncthreads();
        #pragma unroll 4
        for (int i = 0; i < 64; i++) {
            float hv = Hs[i][f];
            #pragma unroll
            for (int r = 0; r < 2; r++) acc[r] += As[i][g * 2 + r] * hv;
        }
    }
    float bb = b2[f];
    #pragma unroll
    for (int r = 0; r < 2; r++) {
        int t = t0 + g * 2 + r;
        g_xp2[t * FOUT + f] = rsqrtf(g_degp[t]) * acc[r] + bb;
    }
}

// out = x_p2[cluster] + relu(alpha) * (x1 @ W_skip + b_skip)
__global__ void __launch_bounds__(256) final_kernel(const int* __restrict__ cluster,
                                                    const float* __restrict__ Wskip,
                                                    const float* __restrict__ bskip,
                                                    const float* __restrict__ alpha,
                                                    float* __restrict__ out) {
    __shared__ float Ws[FH * FOUT];   // 16KB
    __shared__ float xr[8][FH];
    for (int i = threadIdx.x; i < FH * FOUT; i += 256) Ws[i] = Wskip[i];
    __syncthreads();
    float ral = fmaxf(alpha[0], 0.f);
    int warp = threadIdx.x >> 5, lane = threadIdx.x & 31;
    int nwarps = gridDim.x * 8;
    float b0 = bskip[2 * lane], b1v = bskip[2 * lane + 1];
    for (int n = blockIdx.x * 8 + warp; n < NN; n += nwarps) {
        *(float2*)&xr[warp][2 * lane] = *(const float2*)&g_x1[n * FH + 2 * lane];
        __syncwarp();
        int c = cluster[n];
        float2 up = *(const float2*)&g_xp2[c * FOUT + 2 * lane];
        unsigned long long acc = pack2(b0, b1v);
        #pragma unroll 8
        for (int j = 0; j < FH; j++) {
            float xv = xr[warp][j];
            ffma2(acc, pack2(xv, xv), *(const unsigned long long*)&Ws[j * FOUT + 2 * lane]);
        }
        float2 r = unpack2(acc);
        float2 o = make_float2(up.x + ral * r.x, up.y + ral * r.y);
        *(float2*)&out[n * FOUT + 2 * lane] = o;
        __syncwarp();
    }
}

// ---------------- launch ----------------
extern "C" void kernel_launch(void* const* d_in, const int* in_sizes, int n_in,
                              void* d_out, int out_size) {
    const float* x       = (const float*)d_in[0];
    const int*   ei      = (const int*)d_in[1];
    const int*   src     = ei;
    const int*   dst     = ei + NE;
    const int*   cluster = (const int*)d_in[2];
    const float* W1      = (const float*)d_in[3];
    const float* b1      = (const float*)d_in[4];
    const float* W2      = (const float*)d_in[5];
    const float* b2      = (const float*)d_in[6];
    const float* Wsk     = (const float*)d_in[7];
    const float* bsk     = (const float*)d_in[8];
    const float* alpha   = (const float*)d_in[9];
    float* out = (float*)d_out;

    zero_all_kernel<<<(NN * FH + 255) / 256, 256>>>();
    deg_kernel<<<(NE + 255) / 256, 256>>>(dst);
    dinv_kernel<<<(NN + 255) / 256, 256>>>();
    gemm1_kernel<<<592, 256>>>(x, W1);
    edge_agg_kernel<<<(NE * 16) / 256, 256>>>(src, dst);
    x1_pool_kernel<<<(NN * 16 + 255) / 256, 256>>>(cluster, b1);
    a_mat_kernel<<<(NE + 255) / 256, 256>>>(src, dst, cluster);
    a_diag_kernel<<<(KC + 255) / 256, 256>>>();
    degp_kernel<<<dim3(4, 16), 256>>>();
    hp_kernel<<<KC, 64>>>(W2);
    xp2_kernel<<<KC / 8, 256>>>(b2);
    final_kernel<<<592, 256>>>(cluster, Wsk, bsk, alpha, out);
}